// round 10
// baseline (speedup 1.0000x reference)
#include <cuda_runtime.h>
#include <cstdint>
#include <cstddef>

#define BM 128
#define BN 128
#define BK 16
#define THREADS 256
#define PAD 8                    // stride 136 words

#define M_DIM 16384
#define N_DIM 12288
#define K_DIM 4096
#define SEG   4096

#define NT_TILES (N_DIM / BN)   // 96
#define MT_TILES (M_DIM / BM)   // 128
#define BAND 48                 // N-tiles per L2 band (96MB of B resident)

// XOR swizzle: conflict-free for BOTH fragment LDS and staging STS (see analysis)
static __device__ __forceinline__ int swz(int k, int m) {
    return m ^ ((k & 3) << 1) ^ (((k >> 2) & 3) << 3);
}

static __device__ __forceinline__ uint32_t f2tf32(float x) {
    uint32_t u;
    asm("cvt.rna.tf32.f32 %0, %1;" : "=r"(u) : "f"(x));
    return u;
}

static __device__ __forceinline__ void mma8(float* c, const uint32_t* a, const uint32_t* b) {
    asm volatile(
        "mma.sync.aligned.m16n8k8.row.col.f32.tf32.tf32.f32 "
        "{%0,%1,%2,%3}, {%4,%5,%6,%7}, {%8,%9}, {%0,%1,%2,%3};"
        : "+f"(c[0]), "+f"(c[1]), "+f"(c[2]), "+f"(c[3])
        : "r"(a[0]), "r"(a[1]), "r"(a[2]), "r"(a[3]), "r"(b[0]), "r"(b[1]));
}

__global__ __launch_bounds__(THREADS, 2)
void qkv_tf32_mma_kernel(const float* __restrict__ A,   // [M, K] hidden
                         const float* __restrict__ B,   // [N, K] qkv_proj
                         float* __restrict__ Cout)      // 3 segments of [M, SEG]
{
    // ---- band-swizzled tile coords (B band stays hot in L2) ----
    int tile   = blockIdx.x;
    int band   = tile / (BAND * MT_TILES);
    int within = tile - band * (BAND * MT_TILES);
    int nt     = band * BAND + (within % BAND);
    int mt     = within / BAND;
    const int m0 = mt * BM;
    const int n0 = nt * BN;

    __shared__ uint32_t As[2][BK][BM + PAD];   // tf32 bits, k-major, XOR-swizzled cols
    __shared__ uint32_t Bs[2][BK][BN + PAD];

    const int tid  = threadIdx.x;
    const int wid  = tid >> 5;
    const int lane = tid & 31;
    const int g    = lane >> 2;      // group id 0..7
    const int t4   = lane & 3;       // thread-in-group 0..3

    // warp tile: 2 (m) x 4 (n) warps, each 64x32
    const int mw = (wid & 1) * 64;
    const int nw = (wid >> 1) * 32;

    // global-load mapping: rows lr, lr+64; float4 at k-offset lc
    const int lr = tid >> 2;
    const int lc = (tid & 3) << 2;
    const float* Aptr = A + (size_t)(m0 + lr) * K_DIM + lc;
    const float* Bptr = B + (size_t)(n0 + lr) * K_DIM + lc;

    float acc[4][4][4];
#pragma unroll
    for (int i = 0; i < 4; i++)
#pragma unroll
        for (int j = 0; j < 4; j++)
#pragma unroll
            for (int q = 0; q < 4; q++) acc[i][j][q] = 0.0f;

    const int KT = K_DIM / BK;       // 256

    // ---- prologue: stage k-tile 0 into buffer 0 (swizzled STS, conflict-free) ----
    {
        float4 a0 = *(const float4*)(Aptr);
        float4 a1 = *(const float4*)(Aptr + (size_t)64 * K_DIM);
        float4 b0 = *(const float4*)(Bptr);
        float4 b1 = *(const float4*)(Bptr + (size_t)64 * K_DIM);
        As[0][lc + 0][swz(lc + 0, lr)] = f2tf32(a0.x);
        As[0][lc + 1][swz(lc + 1, lr)] = f2tf32(a0.y);
        As[0][lc + 2][swz(lc + 2, lr)] = f2tf32(a0.z);
        As[0][lc + 3][swz(lc + 3, lr)] = f2tf32(a0.w);
        As[0][lc + 0][swz(lc + 0, lr + 64)] = f2tf32(a1.x);
        As[0][lc + 1][swz(lc + 1, lr + 64)] = f2tf32(a1.y);
        As[0][lc + 2][swz(lc + 2, lr + 64)] = f2tf32(a1.z);
        As[0][lc + 3][swz(lc + 3, lr + 64)] = f2tf32(a1.w);
        Bs[0][lc + 0][swz(lc + 0, lr)] = f2tf32(b0.x);
        Bs[0][lc + 1][swz(lc + 1, lr)] = f2tf32(b0.y);
        Bs[0][lc + 2][swz(lc + 2, lr)] = f2tf32(b0.z);
        Bs[0][lc + 3][swz(lc + 3, lr)] = f2tf32(b0.w);
        Bs[0][lc + 0][swz(lc + 0, lr + 64)] = f2tf32(b1.x);
        Bs[0][lc + 1][swz(lc + 1, lr + 64)] = f2tf32(b1.y);
        Bs[0][lc + 2][swz(lc + 2, lr + 64)] = f2tf32(b1.z);
        Bs[0][lc + 3][swz(lc + 3, lr + 64)] = f2tf32(b1.w);
    }
    __syncthreads();

    int buf = 0;
    for (int kt = 0; kt < KT - 1; kt++) {
        // 1) prefetch next k-tile (LDG latency hidden under 32 mma below)
        const float* ap = Aptr + (size_t)(kt + 1) * BK;
        const float* bp = Bptr + (size_t)(kt + 1) * BK;
        float4 na0 = *(const float4*)(ap);
        float4 na1 = *(const float4*)(ap + (size_t)64 * K_DIM);
        float4 nb0 = *(const float4*)(bp);
        float4 nb1 = *(const float4*)(bp + (size_t)64 * K_DIM);

        // 2) compute: 2 k-steps of 8, 16 mma each (swizzled LDS, conflict-free)
#pragma unroll
        for (int ks = 0; ks < 2; ks++) {
            const int k0 = ks * 8;
            const int ka = k0 + t4;
            const int kb = k0 + t4 + 4;
            uint32_t a[4][4], b[4][2];
#pragma unroll
            for (int i = 0; i < 4; i++) {
                const int m = mw + i * 16 + g;
                a[i][0] = As[buf][ka][swz(ka, m)];
                a[i][1] = As[buf][ka][swz(ka, m + 8)];
                a[i][2] = As[buf][kb][swz(kb, m)];
                a[i][3] = As[buf][kb][swz(kb, m + 8)];
            }
#pragma unroll
            for (int j = 0; j < 4; j++) {
                const int n = nw + j * 8 + g;
                b[j][0] = Bs[buf][ka][swz(ka, n)];
                b[j][1] = Bs[buf][kb][swz(kb, n)];
            }
#pragma unroll
            for (int i = 0; i < 4; i++)
#pragma unroll
                for (int j = 0; j < 4; j++) mma8(acc[i][j], a[i], b[j]);
        }

        // 3) stage prefetched tile into other buffer (swizzled STS, conflict-free)
        const int nb = buf ^ 1;
        As[nb][lc + 0][swz(lc + 0, lr)] = f2tf32(na0.x);
        As[nb][lc + 1][swz(lc + 1, lr)] = f2tf32(na0.y);
        As[nb][lc + 2][swz(lc + 2, lr)] = f2tf32(na0.z);
        As[nb][lc + 3][swz(lc + 3, lr)] = f2tf32(na0.w);
        As[nb][lc + 0][swz(lc + 0, lr + 64)] = f2tf32(na1.x);
        As[nb][lc + 1][swz(lc + 1, lr + 64)] = f2tf32(na1.y);
        As[nb][lc + 2][swz(lc + 2, lr + 64)] = f2tf32(na1.z);
        As[nb][lc + 3][swz(lc + 3, lr + 64)] = f2tf32(na1.w);
        Bs[nb][lc + 0][swz(lc + 0, lr)] = f2tf32(nb0.x);
        Bs[nb][lc + 1][swz(lc + 1, lr)] = f2tf32(nb0.y);
        Bs[nb][lc + 2][swz(lc + 2, lr)] = f2tf32(nb0.z);
        Bs[nb][lc + 3][swz(lc + 3, lr)] = f2tf32(nb0.w);
        Bs[nb][lc + 0][swz(lc + 0, lr + 64)] = f2tf32(nb1.x);
        Bs[nb][lc + 1][swz(lc + 1, lr + 64)] = f2tf32(nb1.y);
        Bs[nb][lc + 2][swz(lc + 2, lr + 64)] = f2tf32(nb1.z);
        Bs[nb][lc + 3][swz(lc + 3, lr + 64)] = f2tf32(nb1.w);

        __syncthreads();
        buf ^= 1;
    }

    // peeled last k-tile
#pragma unroll
    for (int ks = 0; ks < 2; ks++) {
        const int k0 = ks * 8;
        const int ka = k0 + t4;
        const int kb = k0 + t4 + 4;
        uint32_t a[4][4], b[4][2];
#pragma unroll
        for (int i = 0; i < 4; i++) {
            const int m = mw + i * 16 + g;
            a[i][0] = As[buf][ka][swz(ka, m)];
            a[i][1] = As[buf][ka][swz(ka, m + 8)];
            a[i][2] = As[buf][kb][swz(kb, m)];
            a[i][3] = As[buf][kb][swz(kb, m + 8)];
        }
#pragma unroll
        for (int j = 0; j < 4; j++) {
            const int n = nw + j * 8 + g;
            b[j][0] = Bs[buf][ka][swz(ka, n)];
            b[j][1] = Bs[buf][kb][swz(kb, n)];
        }
#pragma unroll
        for (int i = 0; i < 4; i++)
#pragma unroll
            for (int j = 0; j < 4; j++) mma8(acc[i][j], a[i], b[j]);
    }

    // ---- epilogue: c frag (g, 2*t4) layout; float2 streaming stores ----
    const int seg = n0 >> 12;
    const int cbase = (n0 & (SEG - 1)) + nw + 2 * t4;
    float* outseg = Cout + (size_t)seg * ((size_t)M_DIM * SEG);

#pragma unroll
    for (int i = 0; i < 4; i++) {
        const int mrow = m0 + mw + i * 16 + g;
        float* r0 = outseg + (size_t)mrow * SEG + cbase;
        float* r1 = outseg + (size_t)(mrow + 8) * SEG + cbase;
#pragma unroll
        for (int j = 0; j < 4; j++) {
            __stcs((float2*)(r0 + j * 8), make_float2(acc[i][j][0], acc[i][j][1]));
            __stcs((float2*)(r1 + j * 8), make_float2(acc[i][j][2], acc[i][j][3]));
        }
    }
}

extern "C" void kernel_launch(void* const* d_in, const int* in_sizes, int n_in,
                              void* d_out, int out_size) {
    const float* hidden = (const float*)d_in[0];   // [16384, 4096] f32
    const float* qkvw   = (const float*)d_in[1];   // [12288, 4096] f32
    (void)in_sizes; (void)n_in; (void)out_size;    // position_ids unused (identity RoPE)
    float* out = (float*)d_out;

    qkv_tf32_mma_kernel<<<NT_TILES * MT_TILES, THREADS>>>(hidden, qkvw, out);
}